// round 4
// baseline (speedup 1.0000x reference)
#include <cuda_runtime.h>
#include <math.h>

#define NB    64
#define NC    256
#define HW    4096            // 64*64
#define NPLANES 16384
#define G     4               // planes per group (64 KB smem)
#define NGROUPS (NPLANES / G) // 4096
#define HIDD  16
#define NCOND 32
#define RHID  64
#define TPB   256
#define GRID  (148 * 3)       // 3 blocks/SM, smem-limited

// ---- scratch (no allocations allowed) ----
__device__ float g_semantic[NPLANES];
__device__ float g_scale[NPLANES];
__device__ int   g_ctr;
__device__ int   g_batch_done[NB];
__device__ int   g_ready[NB];

struct Scratch {
    float sem[NC];
    float cond[NCOND];
    float fusedv[HIDD];
    float w[NC];
    float r1[RHID];
    float r2[RHID];
    float red[32];
    int   bc;      // broadcast group idx
    int   flag;
    int   k;
};

#define SMEM_BYTES (G * HW * 4 + (int)sizeof(Scratch))

// ---------------------------------------------------------------------------
__global__ void init_kernel() {
    const int t = threadIdx.x;
    if (t == 0) g_ctr = 0;
    if (t < NB) { g_batch_done[t] = 0; g_ready[t] = 0; }
}

// ---------------------------------------------------------------------------
// full select for batch b, one block (256 threads). Identical math to the
// proven 3-kernel version.
__device__ __forceinline__ void do_select(
    int b, int t, Scratch& sm,
    const float* __restrict__ base_cr,
    const float* __restrict__ embed,  const float* __restrict__ snr_w1,
    const float* __restrict__ snr_b1, const float* __restrict__ snr_w2,
    const float* __restrict__ snr_b2, const float* __restrict__ sem_w,
    const float* __restrict__ cond_w, const float* __restrict__ out_w,
    const float* __restrict__ r_w1,   const float* __restrict__ r_b1,
    const float* __restrict__ r_w2,   const float* __restrict__ r_b2,
    const float* __restrict__ r_w3,   const float* __restrict__ r_b3,
    const int*   __restrict__ channel_idx, const int* __restrict__ snr_db,
    float* __restrict__ out_cr)
{
    sm.sem[t] = __ldcg(&g_semantic[b * NC + t]);

    if (t < HIDD) sm.cond[t] = embed[channel_idx[0] * 16 + t];
    if (t >= 32 && t < 48) {
        const int i = t - 32;
        const float snr_norm = (float)snr_db[0] / 28.0f;
        float acc = snr_b2[i];
#pragma unroll
        for (int j = 0; j < 16; ++j) {
            float hj = fmaxf(snr_norm * snr_w1[j] + snr_b1[j], 0.0f);
            acc += hj * snr_w2[i * 16 + j];
        }
        sm.cond[16 + i] = fmaxf(acc, 0.0f);
    }
    __syncthreads();

    if (t < HIDD) {
        float acc = 0.0f;
        for (int c = 0; c < NC; ++c)    acc += sm.sem[c]  * sem_w[t * NC + c];
        for (int j = 0; j < NCOND; ++j) acc += sm.cond[j] * cond_w[t * NCOND + j];
        sm.fusedv[t] = fmaxf(acc, 0.0f);
    }
    if (t < RHID) {
        float acc = r_b1[t];
        const float* __restrict__ wr = r_w1 + t * (NC + NCOND);
        for (int j = 0; j < NC; ++j)    acc += sm.sem[j]  * wr[j];
        for (int j = 0; j < NCOND; ++j) acc += sm.cond[j] * wr[NC + j];
        sm.r1[t] = fmaxf(acc, 0.0f);
    }
    __syncthreads();

    {
        float acc = 0.0f;
#pragma unroll
        for (int h = 0; h < HIDD; ++h) acc += sm.fusedv[h] * out_w[t * HIDD + h];
        sm.w[t] = 1.0f / (1.0f + expf(-acc));
    }
    if (t < RHID) {
        float acc = r_b2[t];
#pragma unroll
        for (int j = 0; j < RHID; ++j) acc += sm.r1[j] * r_w2[t * RHID + j];
        sm.r2[t] = fmaxf(acc, 0.0f);
    }
    __syncthreads();

    if (t == 0) {
        float acc = r_b3[0];
#pragma unroll
        for (int j = 0; j < RHID; ++j) acc += sm.r2[j] * r_w3[j];
        float raw = 1.0f / (1.0f + expf(-acc));
        float dyn = 0.3f + 0.7f * raw;
        float cr  = 0.3f * base_cr[0] + 0.7f * dyn;
        cr = fminf(fmaxf(cr, 0.3f), 1.0f);
        out_cr[b] = cr;
        float crs = fminf(fmaxf(cr, 0.001f), 1.0f);
        int kk = (int)rintf(crs * 256.0f);   // round-half-even == jnp.round
        kk = min(max(kk, 1), 256);
        sm.k = kk;
    }
    __syncthreads();

    // stable descending rank
    const float wc = sm.w[t];
    int rank = 0;
    for (int j = 0; j < NC; ++j) {
        float wj = sm.w[j];
        rank += (wj > wc) || (wj == wc && j < t);
    }
    g_scale[b * NC + t] = (rank < sm.k) ? 1.0f : 0.0f;
    __syncthreads();
}

// ---------------------------------------------------------------------------
__global__ void __launch_bounds__(TPB) fused_kernel(
    const float* __restrict__ x,
    const float* __restrict__ base_cr,
    const float* __restrict__ embed,  const float* __restrict__ snr_w1,
    const float* __restrict__ snr_b1, const float* __restrict__ snr_w2,
    const float* __restrict__ snr_b2, const float* __restrict__ sem_w,
    const float* __restrict__ cond_w, const float* __restrict__ out_w,
    const float* __restrict__ r_w1,   const float* __restrict__ r_b1,
    const float* __restrict__ r_w2,   const float* __restrict__ r_b2,
    const float* __restrict__ r_w3,   const float* __restrict__ r_b3,
    const int*   __restrict__ channel_idx, const int* __restrict__ snr_db,
    float* __restrict__ y, float* __restrict__ out_cr)
{
    extern __shared__ float smem[];
    float4* plane_sm = reinterpret_cast<float4*>(smem);        // G*HW floats
    Scratch& sm = *reinterpret_cast<Scratch*>(smem + G * HW);
    const int t = threadIdx.x;
    const int warp = t >> 5, lane = t & 31;

    for (;;) {
        // ---- grab a group of G contiguous planes (same batch) ----
        if (t == 0) sm.bc = atomicAdd(&g_ctr, 1);
        __syncthreads();
        const int g = sm.bc;
        __syncthreads();
        if (g >= NGROUPS) break;
        const int p0 = g * G;
        const int b  = p0 >> 8;

        // ---- single-pass: load planes to smem + per-plane sums ----
        float psum[G];
#pragma unroll
        for (int i = 0; i < G; ++i) {
            const float4* __restrict__ xi =
                reinterpret_cast<const float4*>(x + (size_t)(p0 + i) * HW);
            float s = 0.0f;
#pragma unroll
            for (int j = 0; j < 4; ++j) {
                float4 v = __ldcs(&xi[t + 256 * j]);
                plane_sm[i * 1024 + t + 256 * j] = v;
                s += (v.x + v.y) + (v.z + v.w);
            }
            psum[i] = s;
        }
#pragma unroll
        for (int i = 0; i < G; ++i) {
#pragma unroll
            for (int o = 16; o > 0; o >>= 1)
                psum[i] += __shfl_down_sync(0xffffffffu, psum[i], o);
            if (lane == 0) sm.red[warp * G + i] = psum[i];
        }
        __syncthreads();
        if (t < G) {
            float tot = 0.0f;
#pragma unroll
            for (int w8 = 0; w8 < 8; ++w8) tot += sm.red[w8 * G + t];
            g_semantic[p0 + t] = tot * (1.0f / 4096.0f);
        }
        __syncthreads();

        // ---- mark progress; last group of the batch runs select ----
        if (t == 0) {
            __threadfence();
            int old = atomicAdd(&g_batch_done[b], G);
            sm.flag = (old == NC - G);
            if (sm.flag) __threadfence();     // acquire others' semantic stores
        }
        __syncthreads();
        if (sm.flag) {
            __syncthreads();
            do_select(b, t, sm, base_cr, embed, snr_w1, snr_b1, snr_w2,
                      snr_b2, sem_w, cond_w, out_w, r_w1, r_b1, r_w2, r_b2,
                      r_w3, r_b3, channel_idx, snr_db, out_cr);
            if (t == 0) {
                __threadfence();              // release g_scale / out_cr
                atomicExch(&g_ready[b], 1);
            }
        }
        __syncthreads();

        // ---- wait for the batch's mask ----
        if (t == 0) {
            while (atomicAdd(&g_ready[b], 0) == 0) __nanosleep(100);
            __threadfence();                  // acquire g_scale
        }
        __syncthreads();

        // ---- write y from smem (or zeros) ----
#pragma unroll
        for (int i = 0; i < G; ++i) {
            const float sc = __ldcg(&g_scale[p0 + i]);
            float4* __restrict__ yo =
                reinterpret_cast<float4*>(y + (size_t)(p0 + i) * HW);
            if (sc != 0.0f) {
#pragma unroll
                for (int j = 0; j < 4; ++j)
                    __stcs(&yo[t + 256 * j], plane_sm[i * 1024 + t + 256 * j]);
            } else {
                const float4 z = make_float4(0.f, 0.f, 0.f, 0.f);
#pragma unroll
                for (int j = 0; j < 4; ++j)
                    __stcs(&yo[t + 256 * j], z);
            }
        }
        __syncthreads();   // smem reusable next iteration
    }
}

// ---------------------------------------------------------------------------
extern "C" void kernel_launch(void* const* d_in, const int* in_sizes, int n_in,
                              void* d_out, int out_size) {
    const float* x       = (const float*)d_in[0];
    const float* base_cr = (const float*)d_in[1];
    const float* embed   = (const float*)d_in[2];
    const float* snr_w1  = (const float*)d_in[3];
    const float* snr_b1  = (const float*)d_in[4];
    const float* snr_w2  = (const float*)d_in[5];
    const float* snr_b2  = (const float*)d_in[6];
    const float* sem_w   = (const float*)d_in[7];
    const float* cond_w  = (const float*)d_in[8];
    const float* out_w   = (const float*)d_in[9];
    const float* r_w1    = (const float*)d_in[10];
    const float* r_b1    = (const float*)d_in[11];
    const float* r_w2    = (const float*)d_in[12];
    const float* r_b2    = (const float*)d_in[13];
    const float* r_w3    = (const float*)d_in[14];
    const float* r_b3    = (const float*)d_in[15];
    const int*   ch_idx  = (const int*)d_in[16];
    const int*   snr_db  = (const int*)d_in[17];

    float* y      = (float*)d_out;
    float* out_cr = y + (size_t)NPLANES * HW;   // cr_values appended after y

    static bool attr_set = false;
    if (!attr_set) {
        cudaFuncSetAttribute(fused_kernel,
                             cudaFuncAttributeMaxDynamicSharedMemorySize,
                             SMEM_BYTES);
        attr_set = true;
    }

    init_kernel<<<1, 64>>>();
    fused_kernel<<<GRID, TPB, SMEM_BYTES>>>(
        x, base_cr, embed, snr_w1, snr_b1, snr_w2, snr_b2, sem_w, cond_w,
        out_w, r_w1, r_b1, r_w2, r_b2, r_w3, r_b3, ch_idx, snr_db, y, out_cr);
}

// round 5
// speedup vs baseline: 3.8118x; 3.8118x over previous
#include <cuda_runtime.h>
#include <math.h>

#define NB    64
#define NC    256
#define HW    4096            // 64*64
#define NPLANES 16384
#define HIDD  16
#define NCOND 32
#define RHID  64

// ---- scratch (no allocations allowed) ----
__device__ float g_semantic[NPLANES];
__device__ float g_scale[NPLANES];

// ---------------------------------------------------------------------------
// Pass 1: y = x (streaming copy) + per-plane sum. 16384 blocks x 256 threads.
// Each thread handles 4 float4 (16 floats); the copy IS the GAP read.
// ---------------------------------------------------------------------------
__global__ void __launch_bounds__(256) copy_reduce_kernel(
    const float* __restrict__ x, float* __restrict__ y)
{
    const int bc = blockIdx.x;
    const int t  = threadIdx.x;
    const float4* __restrict__ xi =
        reinterpret_cast<const float4*>(x + (size_t)bc * HW);
    float4* __restrict__ yo =
        reinterpret_cast<float4*>(y + (size_t)bc * HW);

    float s = 0.0f;
#pragma unroll
    for (int j = 0; j < 4; ++j) {
        float4 v = __ldcs(&xi[t + 256 * j]);
        __stcs(&yo[t + 256 * j], v);
        s += (v.x + v.y) + (v.z + v.w);
    }
#pragma unroll
    for (int o = 16; o > 0; o >>= 1)
        s += __shfl_down_sync(0xffffffffu, s, o);

    __shared__ float ws[8];
    if ((t & 31) == 0) ws[t >> 5] = s;
    __syncthreads();
    if (t == 0) {
        float tot = ((ws[0] + ws[1]) + (ws[2] + ws[3]))
                  + ((ws[4] + ws[5]) + (ws[6] + ws[7]));
        g_semantic[bc] = tot * (1.0f / 4096.0f);
    }
}

// ---------------------------------------------------------------------------
// Pass 2: per-batch tiny MLPs + top-k mask. 64 blocks x 256 threads.
// ---------------------------------------------------------------------------
__global__ void select_kernel(
    const float* __restrict__ base_cr,
    const float* __restrict__ embed,     // [3,16]
    const float* __restrict__ snr_w1,    // [16,1]
    const float* __restrict__ snr_b1,    // [16]
    const float* __restrict__ snr_w2,    // [16,16]
    const float* __restrict__ snr_b2,    // [16]
    const float* __restrict__ sem_w,     // [16,256]
    const float* __restrict__ cond_w,    // [16,32]
    const float* __restrict__ out_w,     // [256,16]
    const float* __restrict__ r_w1,      // [64,288]
    const float* __restrict__ r_b1,      // [64]
    const float* __restrict__ r_w2,      // [64,64]
    const float* __restrict__ r_b2,      // [64]
    const float* __restrict__ r_w3,      // [1,64]
    const float* __restrict__ r_b3,      // [1]
    const int*   __restrict__ channel_idx,
    const int*   __restrict__ snr_db,
    float* __restrict__ out_cr)
{
    const int b = blockIdx.x;
    const int t = threadIdx.x;

    __shared__ float sem[NC];
    __shared__ float cond[NCOND];
    __shared__ float fused[HIDD];
    __shared__ float w[NC];
    __shared__ float r1[RHID];
    __shared__ float r2[RHID];
    __shared__ int   k_sh;

    sem[t] = g_semantic[b * NC + t];

    if (t < HIDD) {
        cond[t] = embed[channel_idx[0] * 16 + t];
    }
    if (t >= 32 && t < 48) {
        const int i = t - 32;
        const float snr_norm = (float)snr_db[0] / 28.0f;
        float acc = snr_b2[i];
#pragma unroll
        for (int j = 0; j < 16; ++j) {
            float hj = fmaxf(snr_norm * snr_w1[j] + snr_b1[j], 0.0f);
            acc += hj * snr_w2[i * 16 + j];
        }
        cond[16 + i] = fmaxf(acc, 0.0f);
    }
    __syncthreads();

    // fused = relu(sem @ sem_w.T + cond @ cond_w.T)  [16]
    if (t < HIDD) {
        float acc = 0.0f;
        for (int c = 0; c < NC; ++c)    acc += sem[c]  * sem_w[t * NC + c];
        for (int j = 0; j < NCOND; ++j) acc += cond[j] * cond_w[t * NCOND + j];
        fused[t] = fmaxf(acc, 0.0f);
    }

    // rate controller layer 1
    if (t < RHID) {
        float acc = r_b1[t];
        const float* __restrict__ wr = r_w1 + t * (NC + NCOND);
        for (int j = 0; j < NC; ++j)    acc += sem[j]  * wr[j];
        for (int j = 0; j < NCOND; ++j) acc += cond[j] * wr[NC + j];
        r1[t] = fmaxf(acc, 0.0f);
    }
    __syncthreads();

    // weights = sigmoid(fused @ out_w.T)  [256]
    {
        float acc = 0.0f;
#pragma unroll
        for (int h = 0; h < HIDD; ++h) acc += fused[h] * out_w[t * HIDD + h];
        w[t] = 1.0f / (1.0f + expf(-acc));
    }

    // rate controller layer 2
    if (t < RHID) {
        float acc = r_b2[t];
#pragma unroll
        for (int j = 0; j < RHID; ++j) acc += r1[j] * r_w2[t * RHID + j];
        r2[t] = fmaxf(acc, 0.0f);
    }
    __syncthreads();

    if (t == 0) {
        float acc = r_b3[0];
#pragma unroll
        for (int j = 0; j < RHID; ++j) acc += r2[j] * r_w3[j];
        float raw = 1.0f / (1.0f + expf(-acc));
        float dyn = 0.3f + 0.7f * raw;
        float cr  = 0.3f * base_cr[0] + 0.7f * dyn;
        cr = fminf(fmaxf(cr, 0.3f), 1.0f);
        out_cr[b] = cr;
        float crs = fminf(fmaxf(cr, 0.001f), 1.0f);
        int kk = (int)rintf(crs * 256.0f);   // round-half-even == jnp.round
        kk = min(max(kk, 1), 256);
        k_sh = kk;
    }
    __syncthreads();

    // stable descending rank
    const float wc = w[t];
    int rank = 0;
    for (int j = 0; j < NC; ++j) {
        float wj = w[j];
        rank += (wj > wc) || (wj == wc && j < t);
    }
    g_scale[b * NC + t] = (rank < k_sh) ? 1.0f : 0.0f;
}

// ---------------------------------------------------------------------------
// Pass 3: zero out dropped planes. 16384 blocks x 256 threads; kept-plane
// blocks exit after a single 4-byte load.
// ---------------------------------------------------------------------------
__global__ void __launch_bounds__(256) zero_kernel(float* __restrict__ y) {
    const int bc = blockIdx.x;
    if (g_scale[bc] != 0.0f) return;
    const int t = threadIdx.x;
    float4* __restrict__ yo =
        reinterpret_cast<float4*>(y + (size_t)bc * HW);
    const float4 z = make_float4(0.0f, 0.0f, 0.0f, 0.0f);
#pragma unroll
    for (int j = 0; j < 4; ++j)
        __stcs(&yo[t + 256 * j], z);
}

// ---------------------------------------------------------------------------
extern "C" void kernel_launch(void* const* d_in, const int* in_sizes, int n_in,
                              void* d_out, int out_size) {
    const float* x       = (const float*)d_in[0];
    const float* base_cr = (const float*)d_in[1];
    const float* embed   = (const float*)d_in[2];
    const float* snr_w1  = (const float*)d_in[3];
    const float* snr_b1  = (const float*)d_in[4];
    const float* snr_w2  = (const float*)d_in[5];
    const float* snr_b2  = (const float*)d_in[6];
    const float* sem_w   = (const float*)d_in[7];
    const float* cond_w  = (const float*)d_in[8];
    const float* out_w   = (const float*)d_in[9];
    const float* r_w1    = (const float*)d_in[10];
    const float* r_b1    = (const float*)d_in[11];
    const float* r_w2    = (const float*)d_in[12];
    const float* r_b2    = (const float*)d_in[13];
    const float* r_w3    = (const float*)d_in[14];
    const float* r_b3    = (const float*)d_in[15];
    const int*   ch_idx  = (const int*)d_in[16];
    const int*   snr_db  = (const int*)d_in[17];

    float* y      = (float*)d_out;
    float* out_cr = y + (size_t)NPLANES * HW;   // cr_values appended after y

    copy_reduce_kernel<<<NPLANES, 256>>>(x, y);
    select_kernel<<<NB, 256>>>(base_cr, embed, snr_w1, snr_b1, snr_w2, snr_b2,
                               sem_w, cond_w, out_w,
                               r_w1, r_b1, r_w2, r_b2, r_w3, r_b3,
                               ch_idx, snr_db, out_cr);
    zero_kernel<<<NPLANES, 256>>>(y);
}